// round 9
// baseline (speedup 1.0000x reference)
#include <cuda_runtime.h>
#include <cuda_bf16.h>
#include <cstdint>

#define N_NODES 100000
#define N_EDGES 320000
#define DIM 256

#define SCAN_B 256
#define NBLK ((N_NODES + SCAN_B - 1) / SCAN_B)

// ---------------- scratch (no allocations allowed) ----------------
__device__ int   g_deg_out[N_NODES];
__device__ int   g_deg_in[N_NODES];
__device__ float g_inv_out[N_NODES];
__device__ float g_inv_in[N_NODES];
__device__ float g_h[(size_t)N_NODES * DIM];
// CSR (by dst)
__device__ int g_off[N_NODES + 1];
__device__ int g_cur[N_NODES];
__device__ int g_part[NBLK];
__device__ int g_esrc[N_EDGES];
// W transposed to [N,K], bf16 hi/lo
__device__ __nv_bfloat16 g_bt1_hi[DIM * DIM];
__device__ __nv_bfloat16 g_bt1_lo[DIM * DIM];
__device__ __nv_bfloat16 g_bt2_hi[DIM * DIM];
__device__ __nv_bfloat16 g_bt2_lo[DIM * DIM];

// ---------------- helpers ----------------
__device__ __forceinline__ uint32_t smem_u32(const void* p) {
    uint32_t a;
    asm("{ .reg .u64 t; cvta.to.shared.u64 t, %1; cvt.u32.u64 %0, t; }" : "=r"(a) : "l"(p));
    return a;
}
__device__ __forceinline__ void cp16(uint32_t dst, const void* src) {
    asm volatile("cp.async.cg.shared.global [%0], [%1], 16;"
                 :: "r"(dst), "l"(src) : "memory");
}
__device__ __forceinline__ void cp_commit() {
    asm volatile("cp.async.commit_group;" ::: "memory");
}
__device__ __forceinline__ void cp_wait0() {
    asm volatile("cp.async.wait_group 0;" ::: "memory");
}
__device__ __forceinline__ void cp_wait1() {
    asm volatile("cp.async.wait_group 1;" ::: "memory");
}
__device__ __forceinline__ void ldm4(uint32_t* r, uint32_t addr) {
    asm volatile("ldmatrix.sync.aligned.m8n8.x4.shared.b16 {%0,%1,%2,%3}, [%4];"
                 : "=r"(r[0]), "=r"(r[1]), "=r"(r[2]), "=r"(r[3]) : "r"(addr));
}
__device__ __forceinline__ void mma16816(float* c, const uint32_t* a, uint32_t b0, uint32_t b1) {
    asm volatile("mma.sync.aligned.m16n8k16.row.col.f32.bf16.bf16.f32 "
                 "{%0,%1,%2,%3}, {%4,%5,%6,%7}, {%8,%9}, {%0,%1,%2,%3};"
                 : "+f"(c[0]), "+f"(c[1]), "+f"(c[2]), "+f"(c[3])
                 : "r"(a[0]), "r"(a[1]), "r"(a[2]), "r"(a[3]), "r"(b0), "r"(b1));
}
__device__ __forceinline__ uint32_t pack_hi(float x, float y) {
    return (uint32_t)__bfloat16_as_ushort(__float2bfloat16(x)) |
           ((uint32_t)__bfloat16_as_ushort(__float2bfloat16(y)) << 16);
}
__device__ __forceinline__ uint32_t pack_lo(float x, float y) {
    float rx = x - __bfloat162float(__float2bfloat16(x));
    float ry = y - __bfloat162float(__float2bfloat16(y));
    return (uint32_t)__bfloat16_as_ushort(__float2bfloat16(rx)) |
           ((uint32_t)__bfloat16_as_ushort(__float2bfloat16(ry)) << 16);
}
__device__ __forceinline__ void fma4(float4& a, float w, const float4& v) {
    a.x = fmaf(w, v.x, a.x); a.y = fmaf(w, v.y, a.y);
    a.z = fmaf(w, v.z, a.z); a.w = fmaf(w, v.w, a.w);
}
__device__ __forceinline__ void sts_u2(uint32_t addr, uint2 v) {
    asm volatile("st.shared.v2.u32 [%0], {%1, %2};" :: "r"(addr), "r"(v.x), "r"(v.y) : "memory");
}

// ---------------- graph prep ----------------
__global__ void k_init_counts() {
    int i = blockIdx.x * blockDim.x + threadIdx.x;
    if (i < N_NODES) { g_deg_out[i] = 0; g_deg_in[i] = 0; }
}
__global__ void k_count_deg(const int* __restrict__ src, const int* __restrict__ dst) {
    int e = blockIdx.x * blockDim.x + threadIdx.x;
    if (e < N_EDGES) {
        atomicAdd(&g_deg_out[src[e]], 1);
        atomicAdd(&g_deg_in[dst[e]], 1);
    }
}
__global__ void k_scan1() {
    __shared__ int sh[SCAN_B];
    int i = blockIdx.x * SCAN_B + threadIdx.x;
    int v = (i < N_NODES) ? g_deg_in[i] : 0;
    sh[threadIdx.x] = v;
    __syncthreads();
#pragma unroll
    for (int o = 1; o < SCAN_B; o <<= 1) {
        int t = (threadIdx.x >= o) ? sh[threadIdx.x - o] : 0;
        __syncthreads();
        sh[threadIdx.x] += t;
        __syncthreads();
    }
    if (i < N_NODES) g_off[i] = sh[threadIdx.x] - v;
    if (threadIdx.x == SCAN_B - 1) g_part[blockIdx.x] = sh[SCAN_B - 1];
}
__global__ void k_scan2() {
    __shared__ int sh[512];
    int t = threadIdx.x;
    int v = (t < NBLK) ? g_part[t] : 0;
    sh[t] = v;
    __syncthreads();
#pragma unroll
    for (int o = 1; o < 512; o <<= 1) {
        int x = (t >= o) ? sh[t - o] : 0;
        __syncthreads();
        sh[t] += x;
        __syncthreads();
    }
    if (t < NBLK) g_part[t] = sh[t] - v;
}
__global__ void k_scan3_inv() {
    int i = blockIdx.x * SCAN_B + threadIdx.x;
    if (i < N_NODES) {
        int o = g_off[i] + g_part[blockIdx.x];
        g_off[i] = o;
        g_cur[i] = o;
        g_inv_out[i] = rsqrtf(fmaxf((float)g_deg_out[i], 1.0f));
        g_inv_in[i]  = rsqrtf(fmaxf((float)g_deg_in[i], 1.0f));
    }
    if (i == 0) g_off[N_NODES] = N_EDGES;
}
__global__ void k_bucket(const int* __restrict__ src, const int* __restrict__ dst) {
    int e = blockIdx.x * blockDim.x + threadIdx.x;
    if (e < N_EDGES) {
        int p = atomicAdd(&g_cur[dst[e]], 1);
        g_esrc[p] = src[e];
    }
}
__global__ void k_prep_w2(const float* __restrict__ W1, const float* __restrict__ W2) {
    int i = blockIdx.x * blockDim.x + threadIdx.x;
    int layer = i >= DIM * DIM;
    int j = i - layer * DIM * DIM;
    if (i >= 2 * DIM * DIM) return;
    int n = j >> 8, k = j & 255;
    float v = layer ? W2[k * DIM + n] : W1[k * DIM + n];
    __nv_bfloat16 h = __float2bfloat16(v);
    float l = v - __bfloat162float(h);
    if (layer) { g_bt2_hi[j] = h; g_bt2_lo[j] = __float2bfloat16(l); }
    else       { g_bt1_hi[j] = h; g_bt1_lo[j] = __float2bfloat16(l); }
}

// ---------------- fused gather + GEMM, occupancy 2 ----------------
// BM=64, BN=256, 256 threads (8 warps, warp tile 64x32).
// SMEM: A hi 4 chunks x 8KB = 32KB, A lo +32KB (64 rows x 256 K, swizzled).
//       B: 2 stages x (hi 12K + lo 12K), K=16 chunks, 48B row stride at +64K.
// Total 112KB -> 2 CTAs/SM.
#define OFF_ALO  32768
#define OFF_BB   65536
#define BSTG     24576
#define BTERM    12288
#define SMEM_TOT 114688

__global__ __launch_bounds__(256, 1)
void k_fused(const float* __restrict__ feat,
             const __nv_bfloat16* __restrict__ Bh_g,
             const __nv_bfloat16* __restrict__ Bl_g,
             const float* __restrict__ bias, float* __restrict__ out) {
    extern __shared__ char smem[];
    const uint32_t sb = smem_u32(smem);
    const int tid = threadIdx.x, lane = tid & 31, wid = tid >> 5;
    const int wn = wid;                       // 8 n-warps, warp tile 64x32
    const int row0 = blockIdx.x * 64;

    // B chunk prefetch: k16 chunk c = K cols [c*16, c*16+16), stage s.
    // 256 rows x 32B x 2 terms = 4 cp16 per thread.
#define CPB16(s, c)                                                                  \
    {                                                                                \
        _Pragma("unroll")                                                            \
        for (int it = 0; it < 4; it++) {                                             \
            int term = it >> 1, kcu = it & 1;                                        \
            uint32_t dst = sb + OFF_BB + (s) * BSTG + term * BTERM + tid * 48 + kcu * 16; \
            const __nv_bfloat16* srcp = (term ? Bl_g : Bh_g) + tid * DIM + (c) * 16 + kcu * 8; \
            cp16(dst, srcp);                                                         \
        }                                                                            \
        cp_commit();                                                                 \
    }

    CPB16(0, 0);
    CPB16(1, 1);

    // ---------- phase 1: gather 8 nodes per warp into resident A SMEM ----------
    {
        const int pcu = (lane & 15) >> 1;     // 16B unit within 128B chunk-row
        const int subo = (lane & 1) * 8;      // 8B half
        const int ca0 = lane >> 4;            // chunk 0/1 (cols 0-63 / 64-127)
        for (int i = 0; i < 8; i++) {
            int r = wid * 8 + i;              // CTA-local row 0..63
            int node = row0 + r;
            float4 a0 = make_float4(0.f, 0.f, 0.f, 0.f);
            float4 a1 = a0;
            if (node < N_NODES) {
                int e = g_off[node], e1 = g_off[node + 1];
                for (; e + 2 <= e1; e += 2) {
                    int   sA = g_esrc[e], sB2 = g_esrc[e + 1];
                    float wA = g_inv_out[sA], wB = g_inv_out[sB2];
                    const float4* fA = (const float4*)(feat + (size_t)sA * DIM);
                    const float4* fB = (const float4*)(feat + (size_t)sB2 * DIM);
                    float4 vA0 = fA[lane], vA1 = fA[lane + 32];
                    float4 vB0 = fB[lane], vB1 = fB[lane + 32];
                    fma4(a0, wA, vA0); fma4(a1, wA, vA1);
                    fma4(a0, wB, vB0); fma4(a1, wB, vB1);
                }
                if (e < e1) {
                    int s2 = g_esrc[e];
                    float w = g_inv_out[s2];
                    const float4* fr = (const float4*)(feat + (size_t)s2 * DIM);
                    float4 v0 = fr[lane], v1 = fr[lane + 32];
                    fma4(a0, w, v0); fma4(a1, w, v1);
                }
            }
            uint32_t base = sb + r * 128 + ((pcu ^ (r & 7)) << 4) + subo;
            sts_u2(base + ca0 * 8192,
                   make_uint2(pack_hi(a0.x, a0.y), pack_hi(a0.z, a0.w)));
            sts_u2(base + ca0 * 8192 + OFF_ALO,
                   make_uint2(pack_lo(a0.x, a0.y), pack_lo(a0.z, a0.w)));
            sts_u2(base + (2 + ca0) * 8192,
                   make_uint2(pack_hi(a1.x, a1.y), pack_hi(a1.z, a1.w)));
            sts_u2(base + (2 + ca0) * 8192 + OFF_ALO,
                   make_uint2(pack_lo(a1.x, a1.y), pack_lo(a1.z, a1.w)));
        }
    }

    // ---------- phase 2: GEMM over 16 k16 chunks ----------
    float acc[4][4][4];
#pragma unroll
    for (int i = 0; i < 4; i++)
#pragma unroll
        for (int j = 0; j < 4; j++)
#pragma unroll
            for (int k = 0; k < 4; k++) acc[i][j][k] = 0.f;

#pragma unroll
    for (int g = 0; g < 16; g++) {
        if (g == 15) cp_wait0(); else cp_wait1();
        __syncthreads();                      // joins gather on g==0; stage ready

        const int cA = g >> 2, kA = g & 3;
        const uint32_t sta = sb + cA * 8192;
        const uint32_t stb = sb + OFF_BB + (g & 1) * BSTG;

        uint32_t ah[4][4], al[4][4];
#pragma unroll
        for (int fm = 0; fm < 4; fm++) {
            int row = fm * 16 + (lane & 15);
            int kc = kA * 2 + (lane >> 4);
            uint32_t a = sta + row * 128 + ((kc ^ (row & 7)) << 4);
            ldm4(ah[fm], a);
            ldm4(al[fm], a + OFF_ALO);
        }
        uint32_t bh[2][4], bl[2][4];
#pragma unroll
        for (int rg = 0; rg < 2; rg++) {
            int nrow = wn * 32 + rg * 16 + (lane & 7) + ((lane & 16) >> 1);
            int kc = (lane >> 3) & 1;
            uint32_t a = stb + nrow * 48 + kc * 16;
            ldm4(bh[rg], a);
            ldm4(bl[rg], a + BTERM);
        }
#pragma unroll
        for (int fm = 0; fm < 4; fm++)
#pragma unroll
            for (int fn = 0; fn < 4; fn++) {
                int rg = fn >> 1, o = (fn & 1) * 2;
                mma16816(acc[fm][fn], ah[fm], bh[rg][o], bh[rg][o + 1]);
                mma16816(acc[fm][fn], ah[fm], bl[rg][o], bl[rg][o + 1]);
                mma16816(acc[fm][fn], al[fm], bh[rg][o], bh[rg][o + 1]);
            }
        __syncthreads();                      // all warps done with stage g&1
        if (g < 14) CPB16(g & 1, g + 2);
    }

    // ---------- epilogue: dst-norm + bias + relu ----------
#pragma unroll
    for (int fm = 0; fm < 4; fm++) {
        int mbase = row0 + fm * 16 + (lane >> 2);
#pragma unroll
        for (int half = 0; half < 2; half++) {
            int row = mbase + half * 8;
            if (row >= N_NODES) continue;
            float sc = g_inv_in[row];
#pragma unroll
            for (int fn = 0; fn < 4; fn++) {
                int col = wn * 32 + fn * 8 + 2 * (lane & 3);
                float v0 = acc[fm][fn][half * 2 + 0];
                float v1 = acc[fm][fn][half * 2 + 1];
                float2 o;
                o.x = fmaxf(fmaf(v0, sc, bias[col]), 0.f);
                o.y = fmaxf(fmaf(v1, sc, bias[col + 1]), 0.f);
                *(float2*)(out + (size_t)row * DIM + col) = o;
            }
        }
    }
}

// ---------------- launch ----------------
extern "C" void kernel_launch(void* const* d_in, const int* in_sizes, int n_in,
                              void* d_out, int out_size) {
    const int*   src  = (const int*)d_in[0];
    const int*   dst  = (const int*)d_in[1];
    const float* feat = (const float*)d_in[2];
    const float* W1   = (const float*)d_in[3];
    const float* b1   = (const float*)d_in[4];
    const float* W2   = (const float*)d_in[5];
    const float* b2   = (const float*)d_in[6];
    float*       out  = (float*)d_out;

    float* h; cudaGetSymbolAddress((void**)&h, g_h);
    __nv_bfloat16 *bt1h, *bt1l, *bt2h, *bt2l;
    cudaGetSymbolAddress((void**)&bt1h, g_bt1_hi);
    cudaGetSymbolAddress((void**)&bt1l, g_bt1_lo);
    cudaGetSymbolAddress((void**)&bt2h, g_bt2_hi);
    cudaGetSymbolAddress((void**)&bt2l, g_bt2_lo);

    static int smem_set = 0;
    if (!smem_set) {
        cudaFuncSetAttribute(k_fused, cudaFuncAttributeMaxDynamicSharedMemorySize, SMEM_TOT);
        smem_set = 1;
    }

    const int T = 256;
    const int grid = (N_NODES + 63) / 64;

    // ---- prep ----
    k_init_counts<<<(N_NODES + T - 1) / T, T>>>();
    k_count_deg<<<(N_EDGES + T - 1) / T, T>>>(src, dst);
    k_scan1<<<NBLK, SCAN_B>>>();
    k_scan2<<<1, 512>>>();
    k_scan3_inv<<<NBLK, SCAN_B>>>();
    k_bucket<<<(N_EDGES + T - 1) / T, T>>>(src, dst);
    k_prep_w2<<<(2 * DIM * DIM + T - 1) / T, T>>>(W1, W2);

    // ---- layer 1 / layer 2 ----
    k_fused<<<grid, T, SMEM_TOT>>>(feat, bt1h, bt1l, b1, h);
    k_fused<<<grid, T, SMEM_TOT>>>(h,    bt2h, bt2l, b2, out);
}

// round 10
// speedup vs baseline: 1.5777x; 1.5777x over previous
#include <cuda_runtime.h>
#include <cuda_bf16.h>
#include <cstdint>

#define N_NODES 100000
#define N_EDGES 320000
#define DIM 256
#define PAD_ROWS 128

#define SCAN_B 256
#define NBLK ((N_NODES + SCAN_B - 1) / SCAN_B)

// ---------------- scratch (no allocations allowed) ----------------
__device__ int   g_deg_out[N_NODES];
__device__ int   g_deg_in[N_NODES];
__device__ float g_inv_out[N_NODES];
__device__ float g_inv_in[N_NODES];
__device__ float g_h[(size_t)N_NODES * DIM];
// gather output, pre-split bf16 (padded so full GEMM tiles read in-bounds)
__device__ __nv_bfloat16 g_a_hi[(size_t)(N_NODES + PAD_ROWS) * DIM];
__device__ __nv_bfloat16 g_a_lo[(size_t)(N_NODES + PAD_ROWS) * DIM];
// CSR (by dst)
__device__ int g_off[N_NODES + 1];
__device__ int g_cur[N_NODES];
__device__ int g_part[NBLK];
__device__ int g_esrc[N_EDGES];
// W transposed to [N,K], bf16 hi/lo
__device__ __nv_bfloat16 g_bt1_hi[DIM * DIM];
__device__ __nv_bfloat16 g_bt1_lo[DIM * DIM];
__device__ __nv_bfloat16 g_bt2_hi[DIM * DIM];
__device__ __nv_bfloat16 g_bt2_lo[DIM * DIM];

// ---------------- helpers ----------------
__device__ __forceinline__ uint32_t smem_u32(const void* p) {
    uint32_t a;
    asm("{ .reg .u64 t; cvta.to.shared.u64 t, %1; cvt.u32.u64 %0, t; }" : "=r"(a) : "l"(p));
    return a;
}
__device__ __forceinline__ void cp16(uint32_t dst, const void* src) {
    asm volatile("cp.async.cg.shared.global [%0], [%1], 16;"
                 :: "r"(dst), "l"(src) : "memory");
}
__device__ __forceinline__ void cp_commit() {
    asm volatile("cp.async.commit_group;" ::: "memory");
}
__device__ __forceinline__ void cp_wait0() {
    asm volatile("cp.async.wait_group 0;" ::: "memory");
}
__device__ __forceinline__ void ldm4(uint32_t* r, uint32_t addr) {
    asm volatile("ldmatrix.sync.aligned.m8n8.x4.shared.b16 {%0,%1,%2,%3}, [%4];"
                 : "=r"(r[0]), "=r"(r[1]), "=r"(r[2]), "=r"(r[3]) : "r"(addr));
}
__device__ __forceinline__ void mma16816(float* c, const uint32_t* a, uint32_t b0, uint32_t b1) {
    asm volatile("mma.sync.aligned.m16n8k16.row.col.f32.bf16.bf16.f32 "
                 "{%0,%1,%2,%3}, {%4,%5,%6,%7}, {%8,%9}, {%0,%1,%2,%3};"
                 : "+f"(c[0]), "+f"(c[1]), "+f"(c[2]), "+f"(c[3])
                 : "r"(a[0]), "r"(a[1]), "r"(a[2]), "r"(a[3]), "r"(b0), "r"(b1));
}
__device__ __forceinline__ uint32_t pack_hi(float x, float y) {
    return (uint32_t)__bfloat16_as_ushort(__float2bfloat16(x)) |
           ((uint32_t)__bfloat16_as_ushort(__float2bfloat16(y)) << 16);
}
__device__ __forceinline__ uint32_t pack_lo(float x, float y) {
    float rx = x - __bfloat162float(__float2bfloat16(x));
    float ry = y - __bfloat162float(__float2bfloat16(y));
    return (uint32_t)__bfloat16_as_ushort(__float2bfloat16(rx)) |
           ((uint32_t)__bfloat16_as_ushort(__float2bfloat16(ry)) << 16);
}
__device__ __forceinline__ void st_cs_u2(void* p, uint2 v) {
    asm volatile("st.global.cs.v2.u32 [%0], {%1, %2};"
                 :: "l"(p), "r"(v.x), "r"(v.y) : "memory");
}
__device__ __forceinline__ void fma4(float4& a, float w, const float4& v) {
    a.x = fmaf(w, v.x, a.x); a.y = fmaf(w, v.y, a.y);
    a.z = fmaf(w, v.z, a.z); a.w = fmaf(w, v.w, a.w);
}

// ---------------- graph prep ----------------
__global__ void k_init_counts() {
    int i = blockIdx.x * blockDim.x + threadIdx.x;
    if (i < N_NODES) { g_deg_out[i] = 0; g_deg_in[i] = 0; }
}
__global__ void k_count_deg(const int* __restrict__ src, const int* __restrict__ dst) {
    int e = blockIdx.x * blockDim.x + threadIdx.x;
    if (e < N_EDGES) {
        atomicAdd(&g_deg_out[src[e]], 1);
        atomicAdd(&g_deg_in[dst[e]], 1);
    }
}
__global__ void k_scan1() {
    __shared__ int sh[SCAN_B];
    int i = blockIdx.x * SCAN_B + threadIdx.x;
    int v = (i < N_NODES) ? g_deg_in[i] : 0;
    sh[threadIdx.x] = v;
    __syncthreads();
#pragma unroll
    for (int o = 1; o < SCAN_B; o <<= 1) {
        int t = (threadIdx.x >= o) ? sh[threadIdx.x - o] : 0;
        __syncthreads();
        sh[threadIdx.x] += t;
        __syncthreads();
    }
    if (i < N_NODES) g_off[i] = sh[threadIdx.x] - v;
    if (threadIdx.x == SCAN_B - 1) g_part[blockIdx.x] = sh[SCAN_B - 1];
}
__global__ void k_scan2() {
    __shared__ int sh[512];
    int t = threadIdx.x;
    int v = (t < NBLK) ? g_part[t] : 0;
    sh[t] = v;
    __syncthreads();
#pragma unroll
    for (int o = 1; o < 512; o <<= 1) {
        int x = (t >= o) ? sh[t - o] : 0;
        __syncthreads();
        sh[t] += x;
        __syncthreads();
    }
    if (t < NBLK) g_part[t] = sh[t] - v;
}
__global__ void k_scan3_inv() {
    int i = blockIdx.x * SCAN_B + threadIdx.x;
    if (i < N_NODES) {
        int o = g_off[i] + g_part[blockIdx.x];
        g_off[i] = o;
        g_cur[i] = o;
        g_inv_out[i] = rsqrtf(fmaxf((float)g_deg_out[i], 1.0f));
        g_inv_in[i]  = rsqrtf(fmaxf((float)g_deg_in[i], 1.0f));
    }
    if (i == 0) g_off[N_NODES] = N_EDGES;
}
__global__ void k_bucket(const int* __restrict__ src, const int* __restrict__ dst) {
    int e = blockIdx.x * blockDim.x + threadIdx.x;
    if (e < N_EDGES) {
        int p = atomicAdd(&g_cur[dst[e]], 1);
        g_esrc[p] = src[e];
    }
}
__global__ void k_prep_w2(const float* __restrict__ W1, const float* __restrict__ W2) {
    int i = blockIdx.x * blockDim.x + threadIdx.x;
    int layer = i >= DIM * DIM;
    int j = i - layer * DIM * DIM;
    if (i >= 2 * DIM * DIM) return;
    int n = j >> 8, k = j & 255;
    float v = layer ? W2[k * DIM + n] : W1[k * DIM + n];
    __nv_bfloat16 h = __float2bfloat16(v);
    float l = v - __bfloat162float(h);
    if (layer) { g_bt2_hi[j] = h; g_bt2_lo[j] = __float2bfloat16(l); }
    else       { g_bt1_hi[j] = h; g_bt1_lo[j] = __float2bfloat16(l); }
}

// ---------------- CSR gather + bf16 split, column-tiled ----------------
// One warp per node, HALF the columns per pass (colofs = 0 or 128).
// Working set per pass = 51 MB -> L2-resident.
__global__ __launch_bounds__(256)
void k_gather(const float* __restrict__ feat, int colofs) {
    int node = (blockIdx.x * blockDim.x + threadIdx.x) >> 5;
    int lane = threadIdx.x & 31;
    if (node >= N_NODES) return;
    int e0 = g_off[node], e1 = g_off[node + 1];

    float4 a0 = make_float4(0.f, 0.f, 0.f, 0.f);

    int e = e0;
    for (; e + 2 <= e1; e += 2) {
        int   sA = g_esrc[e], sB = g_esrc[e + 1];
        float wA = g_inv_out[sA], wB = g_inv_out[sB];
        const float4* fA = (const float4*)(feat + (size_t)sA * DIM + colofs);
        const float4* fB = (const float4*)(feat + (size_t)sB * DIM + colofs);
        float4 vA = fA[lane];
        float4 vB = fB[lane];
        fma4(a0, wA, vA);
        fma4(a0, wB, vB);
    }
    if (e < e1) {
        int s = g_esrc[e];
        float w = g_inv_out[s];
        const float4* fr = (const float4*)(feat + (size_t)s * DIM + colofs);
        fma4(a0, w, fr[lane]);
    }
    size_t base = (size_t)node * DIM + colofs + lane * 4;
    st_cs_u2(g_a_hi + base, make_uint2(pack_hi(a0.x, a0.y), pack_hi(a0.z, a0.w)));
    st_cs_u2(g_a_lo + base, make_uint2(pack_lo(a0.x, a0.y), pack_lo(a0.z, a0.w)));
}

// ---------------- HMMA GEMM: out = relu(inv_in[i]*(A@W) + b) ----------------
// BM=128, BN=256, BK=64, 512 threads (16 warps, 2m x 8n, warp tile 64x32).
// Stage: [Ah 16K][Al 16K][Bh 32K][Bl 32K] = 96KB, x2 = 192KB. Pure cp.async.
#define TA 16384
#define OFF_B 32768
#define TB 32768
#define STAGE_B 98304

__global__ __launch_bounds__(512, 1)
void k_gemm_mma(const __nv_bfloat16* __restrict__ Bh_g,
                const __nv_bfloat16* __restrict__ Bl_g,
                const float* __restrict__ bias, float* __restrict__ out) {
    extern __shared__ char smem[];
    const uint32_t sb = smem_u32(smem);
    const int tid = threadIdx.x, lane = tid & 31, wid = tid >> 5;
    const int wm = wid >> 3, wn = wid & 7;
    const int row0 = blockIdx.x * 128;

    float acc[4][4][4];
#pragma unroll
    for (int i = 0; i < 4; i++)
#pragma unroll
        for (int j = 0; j < 4; j++)
#pragma unroll
            for (int k = 0; k < 4; k++) acc[i][j][k] = 0.f;

#define CPALL(s, c)                                                                 \
    {                                                                               \
        _Pragma("unroll")                                                           \
        for (int it = 0; it < 2; it++) {                                            \
            int id = tid + it * 512;                                                \
            int r = id >> 3, pc = id & 7;                                           \
            uint32_t dst = sb + (s) * STAGE_B + r * 128 + ((pc ^ (r & 7)) << 4);    \
            size_t aoff = (size_t)(row0 + r) * DIM + (c) * 64 + pc * 8;             \
            cp16(dst, g_a_hi + aoff);                                               \
            cp16(dst + TA, g_a_lo + aoff);                                          \
        }                                                                           \
        _Pragma("unroll")                                                           \
        for (int it = 0; it < 4; it++) {                                            \
            int id = tid + it * 512;                                                \
            int r = id >> 3, pc = id & 7;                                           \
            uint32_t dst = sb + (s) * STAGE_B + OFF_B + r * 128 + ((pc ^ (r & 7)) << 4); \
            size_t boff = (size_t)r * DIM + (c) * 64 + pc * 8;                      \
            cp16(dst, Bh_g + boff);                                                 \
            cp16(dst + TB, Bl_g + boff);                                            \
        }                                                                           \
        cp_commit();                                                                \
    }

    CPALL(0, 0);

#pragma unroll
    for (int c = 0; c < 4; c++) {
        const int s = c & 1;
        const uint32_t st = sb + s * STAGE_B;
        cp_wait0();
        __syncthreads();
        if (c < 3) CPALL(1 - s, c + 1);

#pragma unroll
        for (int k16 = 0; k16 < 4; k16++) {
            uint32_t ah[4][4], al[4][4];
#pragma unroll
            for (int fm = 0; fm < 4; fm++) {
                int row = wm * 64 + fm * 16 + (lane & 15);
                int kc = k16 * 2 + (lane >> 4);
                uint32_t a = st + row * 128 + ((kc ^ (row & 7)) << 4);
                ldm4(ah[fm], a);
                ldm4(al[fm], a + TA);
            }
            uint32_t bh[2][4], bl[2][4];
#pragma unroll
            for (int rg = 0; rg < 2; rg++) {
                int nrow = wn * 32 + rg * 16 + (lane & 7) + ((lane & 16) >> 1);
                int kc = k16 * 2 + ((lane >> 3) & 1);
                uint32_t a = st + OFF_B + nrow * 128 + ((kc ^ (nrow & 7)) << 4);
                ldm4(bh[rg], a);
                ldm4(bl[rg], a + TB);
            }
#pragma unroll
            for (int fm = 0; fm < 4; fm++)
#pragma unroll
                for (int fn = 0; fn < 4; fn++) {
                    int rg = fn >> 1, o = (fn & 1) * 2;
                    mma16816(acc[fm][fn], ah[fm], bh[rg][o], bh[rg][o + 1]);
                    mma16816(acc[fm][fn], ah[fm], bl[rg][o], bl[rg][o + 1]);
                    mma16816(acc[fm][fn], al[fm], bh[rg][o], bh[rg][o + 1]);
                }
        }
        __syncthreads();
    }

    // epilogue: dst-norm + bias + relu
#pragma unroll
    for (int fm = 0; fm < 4; fm++) {
        int mbase = row0 + wm * 64 + fm * 16 + (lane >> 2);
#pragma unroll
        for (int half = 0; half < 2; half++) {
            int row = mbase + half * 8;
            if (row >= N_NODES) continue;
            float sc = g_inv_in[row];
#pragma unroll
            for (int fn = 0; fn < 4; fn++) {
                int col = wn * 32 + fn * 8 + 2 * (lane & 3);
                float v0 = acc[fm][fn][half * 2 + 0];
                float v1 = acc[fm][fn][half * 2 + 1];
                float2 o;
                o.x = fmaxf(fmaf(v0, sc, bias[col]), 0.f);
                o.y = fmaxf(fmaf(v1, sc, bias[col + 1]), 0.f);
                *(float2*)(out + (size_t)row * DIM + col) = o;
            }
        }
    }
}

// ---------------- launch ----------------
extern "C" void kernel_launch(void* const* d_in, const int* in_sizes, int n_in,
                              void* d_out, int out_size) {
    const int*   src  = (const int*)d_in[0];
    const int*   dst  = (const int*)d_in[1];
    const float* feat = (const float*)d_in[2];
    const float* W1   = (const float*)d_in[3];
    const float* b1   = (const float*)d_in[4];
    const float* W2   = (const float*)d_in[5];
    const float* b2   = (const float*)d_in[6];
    float*       out  = (float*)d_out;

    float* h; cudaGetSymbolAddress((void**)&h, g_h);
    __nv_bfloat16 *bt1h, *bt1l, *bt2h, *bt2l;
    cudaGetSymbolAddress((void**)&bt1h, g_bt1_hi);
    cudaGetSymbolAddress((void**)&bt1l, g_bt1_lo);
    cudaGetSymbolAddress((void**)&bt2h, g_bt2_hi);
    cudaGetSymbolAddress((void**)&bt2l, g_bt2_lo);

    static int smem_set = 0;
    if (!smem_set) {
        cudaFuncSetAttribute(k_gemm_mma, cudaFuncAttributeMaxDynamicSharedMemorySize,
                             2 * STAGE_B);
        smem_set = 1;
    }

    const int T = 256;
    const int gemm_grid = (N_NODES + 127) / 128;
    const int gather_grid = (N_NODES * 32 + T - 1) / T;

    // ---- prep ----
    k_init_counts<<<(N_NODES + T - 1) / T, T>>>();
    k_count_deg<<<(N_EDGES + T - 1) / T, T>>>(src, dst);
    k_scan1<<<NBLK, SCAN_B>>>();
    k_scan2<<<1, 512>>>();
    k_scan3_inv<<<NBLK, SCAN_B>>>();
    k_bucket<<<(N_EDGES + T - 1) / T, T>>>(src, dst);
    k_prep_w2<<<(2 * DIM * DIM + T - 1) / T, T>>>(W1, W2);

    // ---- layer 1 ----
    k_gather<<<gather_grid, T>>>(feat, 0);
    k_gather<<<gather_grid, T>>>(feat, 128);
    k_gemm_mma<<<gemm_grid, 512, 2 * STAGE_B>>>(bt1h, bt1l, b1, h);

    // ---- layer 2 ----
    k_gather<<<gather_grid, T>>>(h, 0);
    k_gather<<<gather_grid, T>>>(h, 128);
    k_gemm_mma<<<gemm_grid, 512, 2 * STAGE_B>>>(bt2h, bt2l, b2, out);
}

// round 11
// speedup vs baseline: 1.6293x; 1.0327x over previous
#include <cuda_runtime.h>
#include <cuda_bf16.h>
#include <cstdint>

#define N_NODES 100000
#define N_EDGES 320000
#define DIM 256
#define PAD_ROWS 128

#define SCAN_B 256
#define NBLK ((N_NODES + SCAN_B - 1) / SCAN_B)

// ---------------- scratch (no allocations allowed) ----------------
__device__ int   g_deg_out[N_NODES];
__device__ int   g_deg_in[N_NODES];
__device__ float g_inv_out[N_NODES];
__device__ float g_inv_in[N_NODES];
__device__ float g_h[(size_t)N_NODES * DIM];
// gather output, pre-split bf16 (padded so full GEMM tiles read in-bounds)
__device__ __nv_bfloat16 g_a_hi[(size_t)(N_NODES + PAD_ROWS) * DIM];
__device__ __nv_bfloat16 g_a_lo[(size_t)(N_NODES + PAD_ROWS) * DIM];
// CSR (by dst)
__device__ int g_off[N_NODES + 1];
__device__ int g_cur[N_NODES];
__device__ int g_part[NBLK];
__device__ int g_esrc[N_EDGES];
// W transposed to [N,K], bf16 hi/lo
__device__ __nv_bfloat16 g_bt1_hi[DIM * DIM];
__device__ __nv_bfloat16 g_bt1_lo[DIM * DIM];
__device__ __nv_bfloat16 g_bt2_hi[DIM * DIM];
__device__ __nv_bfloat16 g_bt2_lo[DIM * DIM];

// ---------------- helpers ----------------
__device__ __forceinline__ uint32_t smem_u32(const void* p) {
    uint32_t a;
    asm("{ .reg .u64 t; cvta.to.shared.u64 t, %1; cvt.u32.u64 %0, t; }" : "=r"(a) : "l"(p));
    return a;
}
__device__ __forceinline__ void cp16(uint32_t dst, const void* src) {
    asm volatile("cp.async.cg.shared.global [%0], [%1], 16;"
                 :: "r"(dst), "l"(src) : "memory");
}
__device__ __forceinline__ void cp_commit() {
    asm volatile("cp.async.commit_group;" ::: "memory");
}
__device__ __forceinline__ void cp_wait0() {
    asm volatile("cp.async.wait_group 0;" ::: "memory");
}
__device__ __forceinline__ void ldm4(uint32_t* r, uint32_t addr) {
    asm volatile("ldmatrix.sync.aligned.m8n8.x4.shared.b16 {%0,%1,%2,%3}, [%4];"
                 : "=r"(r[0]), "=r"(r[1]), "=r"(r[2]), "=r"(r[3]) : "r"(addr));
}
__device__ __forceinline__ void mma16816(float* c, const uint32_t* a, uint32_t b0, uint32_t b1) {
    asm volatile("mma.sync.aligned.m16n8k16.row.col.f32.bf16.bf16.f32 "
                 "{%0,%1,%2,%3}, {%4,%5,%6,%7}, {%8,%9}, {%0,%1,%2,%3};"
                 : "+f"(c[0]), "+f"(c[1]), "+f"(c[2]), "+f"(c[3])
                 : "r"(a[0]), "r"(a[1]), "r"(a[2]), "r"(a[3]), "r"(b0), "r"(b1));
}
__device__ __forceinline__ uint32_t pack_hi(float x, float y) {
    return (uint32_t)__bfloat16_as_ushort(__float2bfloat16(x)) |
           ((uint32_t)__bfloat16_as_ushort(__float2bfloat16(y)) << 16);
}
__device__ __forceinline__ uint32_t pack_lo(float x, float y) {
    float rx = x - __bfloat162float(__float2bfloat16(x));
    float ry = y - __bfloat162float(__float2bfloat16(y));
    return (uint32_t)__bfloat16_as_ushort(__float2bfloat16(rx)) |
           ((uint32_t)__bfloat16_as_ushort(__float2bfloat16(ry)) << 16);
}
__device__ __forceinline__ void st_cs_u2(void* p, uint2 v) {
    asm volatile("st.global.cs.v2.u32 [%0], {%1, %2};"
                 :: "l"(p), "r"(v.x), "r"(v.y) : "memory");
}
__device__ __forceinline__ void fma4(float4& a, float w, const float4& v) {
    a.x = fmaf(w, v.x, a.x); a.y = fmaf(w, v.y, a.y);
    a.z = fmaf(w, v.z, a.z); a.w = fmaf(w, v.w, a.w);
}

// ---------------- graph prep ----------------
__global__ void k_init_counts() {
    int i = blockIdx.x * blockDim.x + threadIdx.x;
    if (i < N_NODES) { g_deg_out[i] = 0; g_deg_in[i] = 0; }
}
// degree count + weight split fused (independent work, one launch)
__global__ void k_count_prep(const int* __restrict__ src, const int* __restrict__ dst,
                             const float* __restrict__ W1, const float* __restrict__ W2) {
    int i = blockIdx.x * blockDim.x + threadIdx.x;
    if (i < N_EDGES) {
        atomicAdd(&g_deg_out[src[i]], 1);
        atomicAdd(&g_deg_in[dst[i]], 1);
    }
    if (i < 2 * DIM * DIM) {
        int layer = i >= DIM * DIM;
        int j = i - layer * DIM * DIM;
        int n = j >> 8, k = j & 255;
        float v = layer ? W2[k * DIM + n] : W1[k * DIM + n];
        __nv_bfloat16 h = __float2bfloat16(v);
        float l = v - __bfloat162float(h);
        if (layer) { g_bt2_hi[j] = h; g_bt2_lo[j] = __float2bfloat16(l); }
        else       { g_bt1_hi[j] = h; g_bt1_lo[j] = __float2bfloat16(l); }
    }
}
__global__ void k_scan1() {
    __shared__ int sh[SCAN_B];
    int i = blockIdx.x * SCAN_B + threadIdx.x;
    int v = (i < N_NODES) ? g_deg_in[i] : 0;
    sh[threadIdx.x] = v;
    __syncthreads();
#pragma unroll
    for (int o = 1; o < SCAN_B; o <<= 1) {
        int t = (threadIdx.x >= o) ? sh[threadIdx.x - o] : 0;
        __syncthreads();
        sh[threadIdx.x] += t;
        __syncthreads();
    }
    if (i < N_NODES) g_off[i] = sh[threadIdx.x] - v;     // block-local exclusive
    if (threadIdx.x == SCAN_B - 1) g_part[blockIdx.x] = sh[SCAN_B - 1];  // block total
}
// per-block prefix of partials computed redundantly (replaces scan2)
__global__ void k_scan3_inv() {
    __shared__ int sred[SCAN_B];
    int t = threadIdx.x, b = blockIdx.x;
    int acc = 0;
    for (int j = t; j < b; j += SCAN_B) acc += g_part[j];
    sred[t] = acc;
    __syncthreads();
#pragma unroll
    for (int o = SCAN_B / 2; o > 0; o >>= 1) {
        if (t < o) sred[t] += sred[t + o];
        __syncthreads();
    }
    int prefix = sred[0];
    int i = b * SCAN_B + t;
    if (i < N_NODES) {
        int o = g_off[i] + prefix;
        g_off[i] = o;
        g_cur[i] = o;
        g_inv_out[i] = rsqrtf(fmaxf((float)g_deg_out[i], 1.0f));
        g_inv_in[i]  = rsqrtf(fmaxf((float)g_deg_in[i], 1.0f));
    }
    if (i == 0) g_off[N_NODES] = N_EDGES;
}
__global__ void k_bucket(const int* __restrict__ src, const int* __restrict__ dst) {
    int e = blockIdx.x * blockDim.x + threadIdx.x;
    if (e < N_EDGES) {
        int p = atomicAdd(&g_cur[dst[e]], 1);
        g_esrc[p] = src[e];
    }
}

// ---------------- CSR gather + bf16 split, cp.async-staged ----------------
// One warp per node; rows staged 4-at-a-time into SMEM via cp.async (4KB/warp
// in flight, no RF cost). Each lane copies and reads only its own chunks ->
// per-thread wait_group(0), no barriers.
__global__ __launch_bounds__(256)
void k_gather(const float* __restrict__ feat) {
    __shared__ float4 stage[8][4][64];          // 8 warps x 4 edges x 1KB = 32KB
    int node = (blockIdx.x * blockDim.x + threadIdx.x) >> 5;
    int lane = threadIdx.x & 31;
    int wid  = (threadIdx.x >> 5) & 7;
    if (node >= N_NODES) return;
    int e0 = g_off[node], e1 = g_off[node + 1];

    const uint32_t stw = smem_u32(&stage[wid][0][0]) + lane * 16;
    float4 a0 = make_float4(0.f, 0.f, 0.f, 0.f);
    float4 a1 = a0;

    for (int base = e0; base < e1; base += 4) {
        int n = e1 - base; if (n > 4) n = 4;
        int s_l = 0;
        if (lane < n) s_l = g_esrc[base + lane];
        float w_l = (lane < n) ? g_inv_out[s_l] : 0.f;
        for (int j = 0; j < n; j++) {
            int sj = __shfl_sync(0xffffffffu, s_l, j);
            const char* row = (const char*)(feat + (size_t)sj * DIM) + lane * 16;
            uint32_t dst = stw + j * 1024;
            cp16(dst, row);
            cp16(dst + 512, row + 512);
        }
        cp_commit();
        cp_wait0();
        for (int j = 0; j < n; j++) {
            float wj = __shfl_sync(0xffffffffu, w_l, j);
            fma4(a0, wj, stage[wid][j][lane]);
            fma4(a1, wj, stage[wid][j][lane + 32]);
        }
    }
    size_t basep = (size_t)node * DIM + lane * 4;
    st_cs_u2(g_a_hi + basep,       make_uint2(pack_hi(a0.x, a0.y), pack_hi(a0.z, a0.w)));
    st_cs_u2(g_a_lo + basep,       make_uint2(pack_lo(a0.x, a0.y), pack_lo(a0.z, a0.w)));
    st_cs_u2(g_a_hi + basep + 128, make_uint2(pack_hi(a1.x, a1.y), pack_hi(a1.z, a1.w)));
    st_cs_u2(g_a_lo + basep + 128, make_uint2(pack_lo(a1.x, a1.y), pack_lo(a1.z, a1.w)));
}

// ---------------- HMMA GEMM: out = relu(inv_in[i]*(A@W) + b) ----------------
// BM=128, BN=256, BK=64, 512 threads (16 warps, 2m x 8n, warp tile 64x32).
// Stage: [Ah 16K][Al 16K][Bh 32K][Bl 32K] = 96KB, x2 = 192KB. Pure cp.async.
#define TA 16384
#define OFF_B 32768
#define TB 32768
#define STAGE_B 98304

__global__ __launch_bounds__(512, 1)
void k_gemm_mma(const __nv_bfloat16* __restrict__ Bh_g,
                const __nv_bfloat16* __restrict__ Bl_g,
                const float* __restrict__ bias, float* __restrict__ out) {
    extern __shared__ char smem[];
    const uint32_t sb = smem_u32(smem);
    const int tid = threadIdx.x, lane = tid & 31, wid = tid >> 5;
    const int wm = wid >> 3, wn = wid & 7;
    const int row0 = blockIdx.x * 128;

    float acc[4][4][4];
#pragma unroll
    for (int i = 0; i < 4; i++)
#pragma unroll
        for (int j = 0; j < 4; j++)
#pragma unroll
            for (int k = 0; k < 4; k++) acc[i][j][k] = 0.f;

#define CPALL(s, c)                                                                 \
    {                                                                               \
        _Pragma("unroll")                                                           \
        for (int it = 0; it < 2; it++) {                                            \
            int id = tid + it * 512;                                                \
            int r = id >> 3, pc = id & 7;                                           \
            uint32_t dst = sb + (s) * STAGE_B + r * 128 + ((pc ^ (r & 7)) << 4);    \
            size_t aoff = (size_t)(row0 + r) * DIM + (c) * 64 + pc * 8;             \
            cp16(dst, g_a_hi + aoff);                                               \
            cp16(dst + TA, g_a_lo + aoff);                                          \
        }                                                                           \
        _Pragma("unroll")                                                           \
        for (int it = 0; it < 4; it++) {                                            \
            int id = tid + it * 512;                                                \
            int r = id >> 3, pc = id & 7;                                           \
            uint32_t dst = sb + (s) * STAGE_B + OFF_B + r * 128 + ((pc ^ (r & 7)) << 4); \
            size_t boff = (size_t)r * DIM + (c) * 64 + pc * 8;                      \
            cp16(dst, Bh_g + boff);                                                 \
            cp16(dst + TB, Bl_g + boff);                                            \
        }                                                                           \
        cp_commit();                                                                \
    }

    CPALL(0, 0);

#pragma unroll
    for (int c = 0; c < 4; c++) {
        const int s = c & 1;
        const uint32_t st = sb + s * STAGE_B;
        cp_wait0();
        __syncthreads();
        if (c < 3) CPALL(1 - s, c + 1);

#pragma unroll
        for (int k16 = 0; k16 < 4; k16++) {
            uint32_t ah[4][4], al[4][4];
#pragma unroll
            for (int fm = 0; fm < 4; fm++) {
                int row = wm * 64 + fm * 16 + (lane & 15);
                int kc = k16 * 2 + (lane >> 4);
                uint32_t a = st + row * 128 + ((kc ^ (row & 7)) << 4);
                ldm4(ah[fm], a);
                ldm4(al[fm], a + TA);
            }
            uint32_t bh[2][4], bl[2][4];
#pragma unroll
            for (int rg = 0; rg < 2; rg++) {
                int nrow = wn * 32 + rg * 16 + (lane & 7) + ((lane & 16) >> 1);
                int kc = k16 * 2 + ((lane >> 3) & 1);
                uint32_t a = st + OFF_B + nrow * 128 + ((kc ^ (nrow & 7)) << 4);
                ldm4(bh[rg], a);
                ldm4(bl[rg], a + TB);
            }
#pragma unroll
            for (int fm = 0; fm < 4; fm++)
#pragma unroll
                for (int fn = 0; fn < 4; fn++) {
                    int rg = fn >> 1, o = (fn & 1) * 2;
                    mma16816(acc[fm][fn], ah[fm], bh[rg][o], bh[rg][o + 1]);
                    mma16816(acc[fm][fn], ah[fm], bl[rg][o], bl[rg][o + 1]);
                    mma16816(acc[fm][fn], al[fm], bh[rg][o], bh[rg][o + 1]);
                }
        }
        __syncthreads();
    }

    // epilogue: dst-norm + bias + relu
#pragma unroll
    for (int fm = 0; fm < 4; fm++) {
        int mbase = row0 + wm * 64 + fm * 16 + (lane >> 2);
#pragma unroll
        for (int half = 0; half < 2; half++) {
            int row = mbase + half * 8;
            if (row >= N_NODES) continue;
            float sc = g_inv_in[row];
#pragma unroll
            for (int fn = 0; fn < 4; fn++) {
                int col = wn * 32 + fn * 8 + 2 * (lane & 3);
                float v0 = acc[fm][fn][half * 2 + 0];
                float v1 = acc[fm][fn][half * 2 + 1];
                float2 o;
                o.x = fmaxf(fmaf(v0, sc, bias[col]), 0.f);
                o.y = fmaxf(fmaf(v1, sc, bias[col + 1]), 0.f);
                *(float2*)(out + (size_t)row * DIM + col) = o;
            }
        }
    }
}

// ---------------- launch ----------------
extern "C" void kernel_launch(void* const* d_in, const int* in_sizes, int n_in,
                              void* d_out, int out_size) {
    const int*   src  = (const int*)d_in[0];
    const int*   dst  = (const int*)d_in[1];
    const float* feat = (const float*)d_in[2];
    const float* W1   = (const float*)d_in[3];
    const float* b1   = (const float*)d_in[4];
    const float* W2   = (const float*)d_in[5];
    const float* b2   = (const float*)d_in[6];
    float*       out  = (float*)d_out;

    float* h; cudaGetSymbolAddress((void**)&h, g_h);
    __nv_bfloat16 *bt1h, *bt1l, *bt2h, *bt2l;
    cudaGetSymbolAddress((void**)&bt1h, g_bt1_hi);
    cudaGetSymbolAddress((void**)&bt1l, g_bt1_lo);
    cudaGetSymbolAddress((void**)&bt2h, g_bt2_hi);
    cudaGetSymbolAddress((void**)&bt2l, g_bt2_lo);

    static int smem_set = 0;
    if (!smem_set) {
        cudaFuncSetAttribute(k_gemm_mma, cudaFuncAttributeMaxDynamicSharedMemorySize,
                             2 * STAGE_B);
        smem_set = 1;
    }

    const int T = 256;
    const int gemm_grid = (N_NODES + 127) / 128;
    const int gather_grid = (N_NODES * 32 + T - 1) / T;

    // ---- prep (5 launches) ----
    k_init_counts<<<(N_NODES + T - 1) / T, T>>>();
    k_count_prep<<<(N_EDGES + T - 1) / T, T>>>(src, dst, W1, W2);
    k_scan1<<<NBLK, SCAN_B>>>();
    k_scan3_inv<<<NBLK, SCAN_B>>>();
    k_bucket<<<(N_EDGES + T - 1) / T, T>>>(src, dst);

    // ---- layer 1 ----
    k_gather<<<gather_grid, T>>>(feat);
    k_gemm_mma<<<gemm_grid, 512, 2 * STAGE_B>>>(bt1h, bt1l, b1, h);

    // ---- layer 2 ----
    k_gather<<<gather_grid, T>>>(h);
    k_gemm_mma<<<gemm_grid, 512, 2 * STAGE_B>>>(bt2h, bt2l, b2, out);
}